// round 11
// baseline (speedup 1.0000x reference)
#include <cuda_runtime.h>
#include <cuda_bf16.h>
#include <cstdint>

// ---------------------------------------------------------------------------
// Fused GCN (BODY_25, fixed topology), HMMA bf16 split GEMM, R11:
//   SPB=5 (M=128), 2 blocks/SM. B (=W2 hi/lo) is pre-arranged in per-lane
//   MMA-fragment order in global memory (L2-hot) and fetched with coalesced
//   __ldg uint4 — no B tiles in SMEM, no W2 copy phase. A (=H1 hi/lo) stays
//   in SMEM for ldmatrix; G overlays A after the GEMM.
// ---------------------------------------------------------------------------

#define NN      25
#define HID     128
#define SPB     5
#define THREADS 512
#define LDA     272          // A tile row stride in BYTES (136 bf16)
#define LDGf    132          // G row stride in floats

typedef unsigned long long u64;

// ---- compile-time normalized CSR (rows = dst), verified R6-R10 ----
__device__ constexpr float RSQ[6] = {0.f, 1.f, 0.70710678118654752f,
                                     0.57735026918962576f, 0.5f,
                                     0.44721359549995794f};
__device__ constexpr int RP[26]  = {0,3,8,10,12,13,15,17,18,21,23,25,28,30,32,
                                    35,37,39,40,41,43,44,45,47,48,49};
__device__ constexpr int COL[49] = {0,15,16, 1,0,2,5,8, 2,3, 3,4, 4, 5,6, 6,7, 7,
                                    8,9,12, 9,10, 10,11, 11,22,24, 12,13, 13,14,
                                    14,19,21, 15,17, 16,18, 17, 18, 19,20, 20, 21,
                                    22,23, 23, 24};
__device__ constexpr int DEGI[25] = {3,5,2,2,1,2,2,1,3,2,2,3,2,2,3,2,2,1,1,2,1,1,2,1,1};
__device__ constexpr int DEGO[25] = {2,1,2,2,2,2,2,2,2,2,2,2,2,2,2,2,2,2,2,2,2,2,2,2,2};
__device__ constexpr float EW(int n, int e) {
    return RSQ[DEGI[n]] * RSQ[DEGO[COL[e]]];
}

// ---- W2 in MMA B-fragment order ----
// u32 index: ((hl*8 + kk)*8 + na2)*128 + lane*4 + q
//   hl: 0=hi 1=lo, kk: k16 step, na2: n-atom pair (0..7), lane 0..31, q 0..3
//   q>>1 selects atom na = na2*2 + (q>>1); q&1 selects b0/b1.
//   t = lane&3, g = lane>>2; n = na*8 + g; k = kk*16 + (q&1)*8 + 2t;
//   value = pack_bf16(W2[k][n], W2[k+1][n])   (low half = lower k)
__device__ __align__(16) uint32_t g_wfrag[16384];   // 64 KB

__global__ void w2_frag_kernel(const float* __restrict__ W2) {
    int i = blockIdx.x * blockDim.x + threadIdx.x;
    if (i >= 16384) return;
    int q    = i & 3;
    int lane = (i >> 2) & 31;
    int na2  = (i >> 7) & 7;
    int kk   = (i >> 10) & 7;
    int hl   = i >> 13;
    int t = lane & 3, g = lane >> 2;
    int na = na2 * 2 + (q >> 1);
    int n  = na * 8 + g;
    int k  = kk * 16 + (q & 1) * 8 + 2 * t;
    float w0 = W2[k * HID + n];
    float w1 = W2[(k + 1) * HID + n];
    __nv_bfloat16 v0, v1;
    if (hl == 0) { v0 = __float2bfloat16(w0); v1 = __float2bfloat16(w1); }
    else {
        __nv_bfloat16 h0 = __float2bfloat16(w0), h1 = __float2bfloat16(w1);
        v0 = __float2bfloat16(w0 - __bfloat162float(h0));
        v1 = __float2bfloat16(w1 - __bfloat162float(h1));
    }
    g_wfrag[i] = ((uint32_t)__bfloat16_as_ushort(v1) << 16)
               | __bfloat16_as_ushort(v0);
}

// ---- SMEM byte layout ----
// A_HI [0, 34816)  A_LO [34816, 69632)   : 128 x 136 bf16 each
// G fp32 (128 x LDGf = 67584 B) overlays A after the GEMM.
// smalls at 69632.
constexpr int A_HI = 0, A_LO = 34816, SMALLB = 69632;
constexpr int FA1 = 0, FW1 = 752, FB1 = 1136, FB2 = 1264,
              FFC = 1392, FBF = 1648, FPL = 1652, FEND = 2932;
constexpr int SMEM_BYTES = SMALLB + FEND * 4;       // 81360

__device__ __forceinline__ uint32_t smem_u32(const void* p) {
    uint32_t a;
    asm("{ .reg .u64 t; cvta.to.shared.u64 t, %1; cvt.u32.u64 %0, t; }"
        : "=r"(a) : "l"(p));
    return a;
}

#define LDSM_X4(r0, r1, r2, r3, addr)                                          \
    asm volatile("ldmatrix.sync.aligned.m8n8.x4.shared.b16 {%0,%1,%2,%3}, [%4];" \
        : "=r"(r0), "=r"(r1), "=r"(r2), "=r"(r3) : "r"(addr))
#define MMA16816(acc, a0, a1, a2, a3, bb0, bb1)                                \
    asm volatile("mma.sync.aligned.m16n8k16.row.col.f32.bf16.bf16.f32 "        \
        "{%0,%1,%2,%3}, {%4,%5,%6,%7}, {%8,%9}, {%0,%1,%2,%3};"                \
        : "+f"((acc)[0]), "+f"((acc)[1]), "+f"((acc)[2]), "+f"((acc)[3])       \
        : "r"(a0), "r"(a1), "r"(a2), "r"(a3), "r"(bb0), "r"(bb1))

__global__ void __launch_bounds__(THREADS, 2)
gcn_hmma_kernel(const float* __restrict__ x,
                const float* __restrict__ W1, const float* __restrict__ b1,
                const float* __restrict__ b2,
                const float* __restrict__ Wfc, const float* __restrict__ bfc,
                float* __restrict__ out, int B)
{
    extern __shared__ __align__(16) unsigned char smb[];
    float* sG  = (float*)smb;                       // overlays A after GEMM
    float* sSm = (float*)(smb + SMALLB);
    float* sA1 = sSm + FA1;
    float* sW1 = sSm + FW1;
    float* sB1 = sSm + FB1;
    float* sB2 = sSm + FB2;
    float* sFc = sSm + FFC;
    float* sBf = sSm + FBF;
    float* sPl = sSm + FPL;

    const uint32_t sb = smem_u32(smb);
    const int tid = threadIdx.x;
    const int wid = tid >> 5, lane = tid & 31;
    const int b0  = blockIdx.x * SPB;
    const int ns  = min(SPB, B - b0);
    const int nsn = ns * NN;                        // <= 125

    // ---- phase 0: stage smalls + AGG1 --------------------------------------
    if (tid < 384) sW1[tid] = W1[tid];
    if (tid < 128) { sB1[tid] = b1[tid]; sB2[tid] = b2[tid]; }
    if (tid < 256) sFc[tid] = Wfc[tid];
    if (tid < 2)   sBf[tid] = bfc[tid];

    if (tid < ns * 3) {          // AGG1 = Ahat @ x (x straight from gmem)
        int s = tid / 3, f = tid - 3 * s;
        const float* xs = x + (long long)(b0 + s) * (NN * 3) + f;
        float xv[NN];
        #pragma unroll
        for (int n = 0; n < NN; n++) xv[n] = __ldg(xs + n * 3);
        #pragma unroll
        for (int n = 0; n < NN; n++) {
            float t = 0.f;
            #pragma unroll
            for (int e = RP[n]; e < RP[n + 1]; e++)
                t = fmaf(EW(n, e), xv[COL[e]], t);
            sA1[(s * NN + n) * 3 + f] = t;
        }
    }
    __syncthreads();

    // ---- phase 1: H1 = relu(AGG1 W1 + b1) -> A_hi/A_lo bf16 tiles ----------
    // thread -> row m = tid>>2 (0..127), j-quarter = (tid&3)*32
    {
        const int m  = tid >> 2;
        const int j0 = (tid & 3) << 5;
        const int mc = min(m, nsn - 1);
        const float a0 = sA1[mc * 3 + 0];
        const float a1 = sA1[mc * 3 + 1];
        const float a2 = sA1[mc * 3 + 2];
        unsigned char* rowH = smb + A_HI + m * LDA;
        unsigned char* rowL = smb + A_LO + m * LDA;
        #pragma unroll
        for (int jj = 0; jj < 32; jj += 2) {
            const int j = j0 + jj;
            float v0 = fmaxf(sB1[j]     + a0 * sW1[j]     + a1 * sW1[128 + j]
                                        + a2 * sW1[256 + j], 0.f);
            float v1 = fmaxf(sB1[j + 1] + a0 * sW1[j + 1] + a1 * sW1[129 + j]
                                        + a2 * sW1[257 + j], 0.f);
            __nv_bfloat16 h0 = __float2bfloat16(v0);
            __nv_bfloat16 h1 = __float2bfloat16(v1);
            __nv_bfloat16 l0 = __float2bfloat16(v0 - __bfloat162float(h0));
            __nv_bfloat16 l1 = __float2bfloat16(v1 - __bfloat162float(h1));
            uint32_t hp = ((uint32_t)__bfloat16_as_ushort(h1) << 16)
                        | __bfloat16_as_ushort(h0);
            uint32_t lp = ((uint32_t)__bfloat16_as_ushort(l1) << 16)
                        | __bfloat16_as_ushort(l0);
            *(uint32_t*)(rowH + j * 2) = hp;
            *(uint32_t*)(rowL + j * 2) = lp;
        }
    }
    __syncthreads();

    // ---- phase 2: split GEMM; A via ldmatrix, B via fragment LDG -----------
    // warp: m-tile mt = wid&7 (16 rows), n-half nh = wid>>3 (64 cols)
    const int mt = wid & 7, nh = wid >> 3;
    const int m0 = mt << 4;

    float acc[8][4];             // [warp-local n-atom][frag]
    #pragma unroll
    for (int j = 0; j < 8; j++)
        #pragma unroll
        for (int q = 0; q < 4; q++) acc[j][q] = 0.f;

    {
        const uint32_t aOff = (uint32_t)(m0 + (lane & 15)) * LDA
                            + ((lane >> 4) << 4);
        const uint32_t aH = sb + A_HI + aOff;
        const uint32_t aL = sb + A_LO + aOff;
        const uint4* fragH = (const uint4*)g_wfrag + (nh << 2) * 32 + lane;
        const uint4* fragL = fragH + 2048 / 4 * 4;   // hl stride = 2048 u32 = 512 uint4

        #pragma unroll 1
        for (int kk = 0; kk < 8; kk++) {
            uint32_t ah[4], al[4];
            LDSM_X4(ah[0], ah[1], ah[2], ah[3], aH + kk * 32);
            LDSM_X4(al[0], al[1], al[2], al[3], aL + kk * 32);
            const uint4* fHk = fragH + (kk << 8) / 4 * 4;   // kk stride = 256 u32 = 64 uint4
            const uint4* fLk = fragL + (kk << 8) / 4 * 4;
            #pragma unroll
            for (int nb = 0; nb < 4; nb++) {
                uint4 bh = __ldg(fHk + (nb << 5));
                uint4 bl = __ldg(fLk + (nb << 5));
                MMA16816(acc[2*nb  ], ah[0], ah[1], ah[2], ah[3], bh.x, bh.y);
                MMA16816(acc[2*nb+1], ah[0], ah[1], ah[2], ah[3], bh.z, bh.w);
                MMA16816(acc[2*nb  ], al[0], al[1], al[2], al[3], bh.x, bh.y);
                MMA16816(acc[2*nb+1], al[0], al[1], al[2], al[3], bh.z, bh.w);
                MMA16816(acc[2*nb  ], ah[0], ah[1], ah[2], ah[3], bl.x, bl.y);
                MMA16816(acc[2*nb+1], ah[0], ah[1], ah[2], ah[3], bl.z, bl.w);
            }
        }
    }
    __syncthreads();    // everyone done reading A tiles

    // ---- phase 3: accs -> G[m][n] fp32 (overlays A region) -----------------
    {
        const int g  = lane >> 2;
        const int t2 = (lane & 3) << 1;
        const int c0 = (nh << 6) + t2;
        #pragma unroll
        for (int na = 0; na < 8; na++) {
            const int col = c0 + (na << 3);
            *(float2*)(sG + (m0 + g)     * LDGf + col) =
                make_float2(acc[na][0], acc[na][1]);
            *(float2*)(sG + (m0 + 8 + g) * LDGf + col) =
                make_float2(acc[na][2], acc[na][3]);
        }
    }
    __syncthreads();

    // ---- phase 4: fused Ahat@G + b2 + relu + mean-pool (float4 reads) ------
    if (tid < ns * (HID / 4)) {
        const int s  = tid >> 5;
        const int j4 = tid & 31;
        const float4* G4 = (const float4*)sG;       // row r: G4[r*(LDGf/4)+j4]
        const int base = s * NN;
        const float4 bb = ((const float4*)sB2)[j4];
        float4 pooled = make_float4(0.f, 0.f, 0.f, 0.f);
        #pragma unroll
        for (int n = 0; n < NN; n++) {
            float4 t = make_float4(0.f, 0.f, 0.f, 0.f);
            #pragma unroll
            for (int e = RP[n]; e < RP[n + 1]; e++) {
                const float w = EW(n, e);
                float4 g = G4[(base + COL[e]) * (LDGf / 4) + j4];
                t.x = fmaf(w, g.x, t.x);
                t.y = fmaf(w, g.y, t.y);
                t.z = fmaf(w, g.z, t.z);
                t.w = fmaf(w, g.w, t.w);
            }
            pooled.x += fmaxf(t.x + bb.x, 0.f);
            pooled.y += fmaxf(t.y + bb.y, 0.f);
            pooled.z += fmaxf(t.z + bb.z, 0.f);
            pooled.w += fmaxf(t.w + bb.w, 0.f);
        }
        pooled.x *= 0.04f; pooled.y *= 0.04f;
        pooled.z *= 0.04f; pooled.w *= 0.04f;
        ((float4*)sPl)[tid] = pooled;
    }
    __syncthreads();

    // ---- phase 5: FC head, one warp per sample -----------------------------
    if (wid < ns) {
        float p0 = 0.f, p1 = 0.f;
        #pragma unroll
        for (int j = lane; j < HID; j += 32) {
            float pv = sPl[wid * HID + j];
            p0 += pv * sFc[j * 2 + 0];
            p1 += pv * sFc[j * 2 + 1];
        }
        #pragma unroll
        for (int o = 16; o; o >>= 1) {
            p0 += __shfl_xor_sync(0xffffffff, p0, o);
            p1 += __shfl_xor_sync(0xffffffff, p1, o);
        }
        if (lane == 0) {
            int b = b0 + wid;
            out[b * 2 + 0] = p0 + sBf[0];
            out[b * 2 + 1] = p1 + sBf[1];
        }
    }
}

extern "C" void kernel_launch(void* const* d_in, const int* in_sizes, int n_in,
                              void* d_out, int out_size)
{
    const float *x = 0, *W1 = 0, *b1 = 0, *W2 = 0, *b2 = 0, *Wfc = 0, *bfc = 0;
    int B = 0;
    for (int i = 0; i < n_in; i++) {
        int s = in_sizes[i];
        if      (s == 16384) W2  = (const float*)d_in[i];
        else if (s == 384)   W1  = (const float*)d_in[i];
        else if (s == 256)   Wfc = (const float*)d_in[i];
        else if (s == 2)     bfc = (const float*)d_in[i];
        else if (s == 128)   { if (!b1) b1 = (const float*)d_in[i];
                               else     b2 = (const float*)d_in[i]; }
        else if (s > 16384)  { x = (const float*)d_in[i]; B = s / (NN * 3); }
    }
    float* out = (float*)d_out;

    w2_frag_kernel<<<32, 512>>>(W2);

    const int grid = (B + SPB - 1) / SPB;
    cudaFuncSetAttribute(gcn_hmma_kernel,
                         cudaFuncAttributeMaxDynamicSharedMemorySize, SMEM_BYTES);
    gcn_hmma_kernel<<<grid, THREADS, SMEM_BYTES>>>(x, W1, b1, b2, Wfc, bfc,
                                                   out, B);
}

// round 12
// speedup vs baseline: 1.4146x; 1.4146x over previous
#include <cuda_runtime.h>
#include <cuda_bf16.h>
#include <cstdint>

// ---------------------------------------------------------------------------
// Fused GCN (BODY_25, fixed topology), HMMA bf16 split GEMM, R12:
//   = R10 (SPB=10, B hi/lo in SMEM, fragment-reuse 32x64 warp tiles)
//   + conflict-free phase 1: lane-owns-4-columns layout, W1/b1 hoisted as
//     LDS.128, broadcast sA1 reads, STS.64 stores. GEMM untouched.
// ---------------------------------------------------------------------------

#define NN      25
#define HID     128
#define SPB     10
#define THREADS 512
#define LDA     272          // A/B tile row stride in BYTES (136 bf16)
#define LDGf    132          // G row stride in floats

typedef unsigned long long u64;

// ---- compile-time normalized CSR (rows = dst), verified R6-R11 ----
__device__ constexpr float RSQ[6] = {0.f, 1.f, 0.70710678118654752f,
                                     0.57735026918962576f, 0.5f,
                                     0.44721359549995794f};
__device__ constexpr int RP[26]  = {0,3,8,10,12,13,15,17,18,21,23,25,28,30,32,
                                    35,37,39,40,41,43,44,45,47,48,49};
__device__ constexpr int COL[49] = {0,15,16, 1,0,2,5,8, 2,3, 3,4, 4, 5,6, 6,7, 7,
                                    8,9,12, 9,10, 10,11, 11,22,24, 12,13, 13,14,
                                    14,19,21, 15,17, 16,18, 17, 18, 19,20, 20, 21,
                                    22,23, 23, 24};
__device__ constexpr int DEGI[25] = {3,5,2,2,1,2,2,1,3,2,2,3,2,2,3,2,2,1,1,2,1,1,2,1,1};
__device__ constexpr int DEGO[25] = {2,1,2,2,2,2,2,2,2,2,2,2,2,2,2,2,2,2,2,2,2,2,2,2,2};
__device__ constexpr float EW(int n, int e) {
    return RSQ[DEGI[n]] * RSQ[DEGO[COL[e]]];
}

// ---- W2 pre-split scratch: [k][n] bf16, padded rows (LDA bytes); hi then lo
__device__ __align__(16) unsigned char g_w2[2 * 128 * LDA];   // 69632 B

__global__ void w2_split_kernel(const float* __restrict__ W2) {
    int i = blockIdx.x * blockDim.x + threadIdx.x;   // i = k*128 + n
    if (i < HID * HID) {
        int k = i >> 7, n = i & 127;
        float w = W2[i];
        __nv_bfloat16 hi = __float2bfloat16(w);
        __nv_bfloat16 lo = __float2bfloat16(w - __bfloat162float(hi));
        uint32_t off = (uint32_t)k * LDA + (uint32_t)n * 2;
        *(__nv_bfloat16*)(g_w2 + off)              = hi;
        *(__nv_bfloat16*)(g_w2 + 128 * LDA + off)  = lo;
    }
}

// ---- SMEM byte layout (as R10) ----
constexpr int A_HI = 0, A_LO = 69632, B_HI = 139264, B_LO = 174080,
              SMALLB = 208896;
constexpr int FA1 = 0, FW1 = 752, FB1 = 1136, FB2 = 1264,
              FFC = 1392, FBF = 1648, FPL = 1652, FEND = 2932;
constexpr int SMEM_BYTES = SMALLB + FEND * 4;       // 220624

__device__ __forceinline__ uint32_t smem_u32(const void* p) {
    uint32_t a;
    asm("{ .reg .u64 t; cvta.to.shared.u64 t, %1; cvt.u32.u64 %0, t; }"
        : "=r"(a) : "l"(p));
    return a;
}

#define LDSM_X4(r0, r1, r2, r3, addr)                                          \
    asm volatile("ldmatrix.sync.aligned.m8n8.x4.shared.b16 {%0,%1,%2,%3}, [%4];" \
        : "=r"(r0), "=r"(r1), "=r"(r2), "=r"(r3) : "r"(addr))
#define LDSM_X4T(r0, r1, r2, r3, addr)                                         \
    asm volatile("ldmatrix.sync.aligned.m8n8.x4.trans.shared.b16 {%0,%1,%2,%3}, [%4];" \
        : "=r"(r0), "=r"(r1), "=r"(r2), "=r"(r3) : "r"(addr))
#define MMA16816(acc, a0, a1, a2, a3, bb0, bb1)                                \
    asm volatile("mma.sync.aligned.m16n8k16.row.col.f32.bf16.bf16.f32 "        \
        "{%0,%1,%2,%3}, {%4,%5,%6,%7}, {%8,%9}, {%0,%1,%2,%3};"                \
        : "+f"((acc)[0]), "+f"((acc)[1]), "+f"((acc)[2]), "+f"((acc)[3])       \
        : "r"(a0), "r"(a1), "r"(a2), "r"(a3), "r"(bb0), "r"(bb1))

__device__ __forceinline__ uint32_t split_pack(float v0, float v1,
                                               uint32_t& lo_pack) {
    __nv_bfloat16 h0 = __float2bfloat16(v0);
    __nv_bfloat16 h1 = __float2bfloat16(v1);
    __nv_bfloat16 l0 = __float2bfloat16(v0 - __bfloat162float(h0));
    __nv_bfloat16 l1 = __float2bfloat16(v1 - __bfloat162float(h1));
    lo_pack = ((uint32_t)__bfloat16_as_ushort(l1) << 16)
            | __bfloat16_as_ushort(l0);
    return ((uint32_t)__bfloat16_as_ushort(h1) << 16)
         | __bfloat16_as_ushort(h0);
}

__global__ void __launch_bounds__(THREADS, 1)
gcn_hmma_kernel(const float* __restrict__ x,
                const float* __restrict__ W1, const float* __restrict__ b1,
                const float* __restrict__ b2,
                const float* __restrict__ Wfc, const float* __restrict__ bfc,
                float* __restrict__ out, int B)
{
    extern __shared__ __align__(16) unsigned char smb[];
    float* sG  = (float*)smb;                       // overlays A after GEMM
    float* sSm = (float*)(smb + SMALLB);
    float* sA1 = sSm + FA1;
    float* sW1 = sSm + FW1;
    float* sB1 = sSm + FB1;
    float* sB2 = sSm + FB2;
    float* sFc = sSm + FFC;
    float* sBf = sSm + FBF;
    float* sPl = sSm + FPL;

    const uint32_t sb = smem_u32(smb);
    const int tid = threadIdx.x;
    const int wid = tid >> 5, lane = tid & 31;
    const int b0  = blockIdx.x * SPB;
    const int ns  = min(SPB, B - b0);
    const int nsn = ns * NN;

    // ---- phase 0: stage smalls, copy pre-split W2 tiles, AGG1 -------------
    if (tid < 384) sW1[tid] = W1[tid];
    if (tid < 128) { sB1[tid] = b1[tid]; sB2[tid] = b2[tid]; }
    if (tid < 256) sFc[tid] = Wfc[tid];
    if (tid < 2)   sBf[tid] = bfc[tid];

    {   // both W2 tiles: 69632 B = 4352 uint4
        const uint4* src = (const uint4*)g_w2;
        uint4* dst = (uint4*)(smb + B_HI);
        #pragma unroll
        for (int i = tid; i < 4352; i += THREADS) dst[i] = src[i];
    }

    if (tid < ns * 3) {          // AGG1 = Ahat @ x (x straight from gmem)
        int s = tid / 3, f = tid - 3 * s;
        const float* xs = x + (long long)(b0 + s) * (NN * 3) + f;
        float xv[NN];
        #pragma unroll
        for (int n = 0; n < NN; n++) xv[n] = __ldg(xs + n * 3);
        #pragma unroll
        for (int n = 0; n < NN; n++) {
            float t = 0.f;
            #pragma unroll
            for (int e = RP[n]; e < RP[n + 1]; e++)
                t = fmaf(EW(n, e), xv[COL[e]], t);
            sA1[(s * NN + n) * 3 + f] = t;
        }
    }
    __syncthreads();

    // ---- phase 1 (REDESIGNED): H1 -> A_hi/A_lo, conflict-free --------------
    // lane owns columns 4l..4l+3 (W1/b1 hoisted as LDS.128);
    // warp owns rows wid*16..wid*16+15; sA1 reads are warp-broadcast;
    // stores are 2x STS.64 per row, conflict-free.
    {
        const float4 w0 = *(const float4*)(sW1 +       4 * lane);
        const float4 w1 = *(const float4*)(sW1 + 128 + 4 * lane);
        const float4 w2 = *(const float4*)(sW1 + 256 + 4 * lane);
        const float4 bb = *(const float4*)(sB1 +       4 * lane);
        unsigned char* baseH = smb + A_HI + 8 * lane;
        unsigned char* baseL = smb + A_LO + 8 * lane;
        #pragma unroll
        for (int r = 0; r < 16; r++) {
            const int m  = (wid << 4) + r;
            const int mc = min(m, nsn - 1);
            const float a0 = sA1[mc * 3 + 0];
            const float a1 = sA1[mc * 3 + 1];
            const float a2 = sA1[mc * 3 + 2];
            float v0 = fmaxf(bb.x + a0 * w0.x + a1 * w1.x + a2 * w2.x, 0.f);
            float v1 = fmaxf(bb.y + a0 * w0.y + a1 * w1.y + a2 * w2.y, 0.f);
            float v2 = fmaxf(bb.z + a0 * w0.z + a1 * w1.z + a2 * w2.z, 0.f);
            float v3 = fmaxf(bb.w + a0 * w0.w + a1 * w1.w + a2 * w2.w, 0.f);
            uint32_t lp0, lp1;
            uint32_t hp0 = split_pack(v0, v1, lp0);
            uint32_t hp1 = split_pack(v2, v3, lp1);
            *(uint2*)(baseH + m * LDA) = make_uint2(hp0, hp1);
            *(uint2*)(baseL + m * LDA) = make_uint2(lp0, lp1);
        }
    }
    __syncthreads();

    // ---- phase 2: split GEMM, fragment-reuse mainloop (unchanged R10) ------
    const int mt = wid & 7, nh = wid >> 3;
    const int m0 = mt << 5;

    float acc[2][8][4];
    #pragma unroll
    for (int i = 0; i < 2; i++)
        #pragma unroll
        for (int j = 0; j < 8; j++)
            #pragma unroll
            for (int q = 0; q < 4; q++) acc[i][j][q] = 0.f;

    {
        const uint32_t aOff = (uint32_t)(m0 + (lane & 15)) * LDA
                            + ((lane >> 4) << 4);
        const uint32_t bOff = (uint32_t)(lane & 15) * LDA
                            + ((lane >> 4) << 4) + (nh << 7);
        const uint32_t aH = sb + A_HI + aOff;
        const uint32_t aL = sb + A_LO + aOff;
        const uint32_t bH = sb + B_HI + bOff;
        const uint32_t bL = sb + B_LO + bOff;

        #pragma unroll 1
        for (int kk = 0; kk < 8; kk++) {
            const uint32_t ka = kk * 32;
            const uint32_t kb = kk * (16 * LDA);
            uint32_t ah0[4], ah1[4], al0[4], al1[4];
            LDSM_X4(ah0[0], ah0[1], ah0[2], ah0[3], aH + ka);
            LDSM_X4(ah1[0], ah1[1], ah1[2], ah1[3], aH + ka + 16 * LDA);
            LDSM_X4(al0[0], al0[1], al0[2], al0[3], aL + ka);
            LDSM_X4(al1[0], al1[1], al1[2], al1[3], aL + ka + 16 * LDA);
            #pragma unroll
            for (int nb = 0; nb < 4; nb++) {
                uint32_t bh[4], bl[4];
                LDSM_X4T(bh[0], bh[1], bh[2], bh[3], bH + kb + nb * 32);
                LDSM_X4T(bl[0], bl[1], bl[2], bl[3], bL + kb + nb * 32);
                MMA16816(acc[0][2*nb  ], ah0[0], ah0[1], ah0[2], ah0[3], bh[0], bh[1]);
                MMA16816(acc[0][2*nb+1], ah0[0], ah0[1], ah0[2], ah0[3], bh[2], bh[3]);
                MMA16816(acc[1][2*nb  ], ah1[0], ah1[1], ah1[2], ah1[3], bh[0], bh[1]);
                MMA16816(acc[1][2*nb+1], ah1[0], ah1[1], ah1[2], ah1[3], bh[2], bh[3]);
                MMA16816(acc[0][2*nb  ], al0[0], al0[1], al0[2], al0[3], bh[0], bh[1]);
                MMA16816(acc[0][2*nb+1], al0[0], al0[1], al0[2], al0[3], bh[2], bh[3]);
                MMA16816(acc[1][2*nb  ], al1[0], al1[1], al1[2], al1[3], bh[0], bh[1]);
                MMA16816(acc[1][2*nb+1], al1[0], al1[1], al1[2], al1[3], bh[2], bh[3]);
                MMA16816(acc[0][2*nb  ], ah0[0], ah0[1], ah0[2], ah0[3], bl[0], bl[1]);
                MMA16816(acc[0][2*nb+1], ah0[0], ah0[1], ah0[2], ah0[3], bl[2], bl[3]);
                MMA16816(acc[1][2*nb  ], ah1[0], ah1[1], ah1[2], ah1[3], bl[0], bl[1]);
                MMA16816(acc[1][2*nb+1], ah1[0], ah1[1], ah1[2], ah1[3], bl[2], bl[3]);
            }
        }
    }
    __syncthreads();

    // ---- phase 3: accs -> G[m][n] fp32 (overlays A region) -----------------
    {
        const int g  = lane >> 2;
        const int t2 = (lane & 3) << 1;
        const int c0 = (nh << 6) + t2;
        #pragma unroll
        for (int ma = 0; ma < 2; ma++) {
            const int r0 = m0 + (ma << 4) + g;
            #pragma unroll
            for (int na = 0; na < 8; na++) {
                const int col = c0 + (na << 3);
                *(float2*)(sG + r0       * LDGf + col) =
                    make_float2(acc[ma][na][0], acc[ma][na][1]);
                *(float2*)(sG + (r0 + 8) * LDGf + col) =
                    make_float2(acc[ma][na][2], acc[ma][na][3]);
            }
        }
    }
    __syncthreads();

    // ---- phase 4: fused Ahat@G + b2 + relu + mean-pool (float4 reads) ------
    if (tid < ns * (HID / 4)) {
        const int s  = tid >> 5;
        const int j4 = tid & 31;
        const float4* G4 = (const float4*)sG;
        const int base = s * NN;
        const float4 bb = ((const float4*)sB2)[j4];
        float4 pooled = make_float4(0.f, 0.f, 0.f, 0.f);
        #pragma unroll
        for (int n = 0; n < NN; n++) {
            float4 t = make_float4(0.f, 0.f, 0.f, 0.f);
            #pragma unroll
            for (int e = RP[n]; e < RP[n + 1]; e++) {
                const float w = EW(n, e);
                float4 g = G4[(base + COL[e]) * (LDGf / 4) + j4];
                t.x = fmaf(w, g.x, t.x);
                t.y = fmaf(w, g.y, t.y);
                t.z = fmaf(w, g.z, t.z);
                t.w = fmaf(w, g.w, t.w);
            }
            pooled.x += fmaxf(t.x + bb.x, 0.f);
            pooled.y += fmaxf(t.y + bb.y, 0.f);
            pooled.z += fmaxf(t.z + bb.z, 0.f);
            pooled.w += fmaxf(t.w + bb.w, 0.f);
        }
        pooled.x *= 0.04f; pooled.y *= 0.04f;
        pooled.z *= 0.04f; pooled.w *= 0.04f;
        ((float4*)sPl)[tid] = pooled;
    }
    __syncthreads();

    // ---- phase 5: FC head, one warp per sample -----------------------------
    if (wid < ns) {
        float p0 = 0.f, p1 = 0.f;
        #pragma unroll
        for (int j = lane; j < HID; j += 32) {
            float pv = sPl[wid * HID + j];
            p0 += pv * sFc[j * 2 + 0];
            p1 += pv * sFc[j * 2 + 1];
        }
        #pragma unroll
        for (int o = 16; o; o >>= 1) {
            p0 += __shfl_xor_sync(0xffffffff, p0, o);
            p1 += __shfl_xor_sync(0xffffffff, p1, o);
        }
        if (lane == 0) {
            int b = b0 + wid;
            out[b * 2 + 0] = p0 + sBf[0];
            out[b * 2 + 1] = p1 + sBf[1];
        }
    }
}

extern "C" void kernel_launch(void* const* d_in, const int* in_sizes, int n_in,
                              void* d_out, int out_size)
{
    const float *x = 0, *W1 = 0, *b1 = 0, *W2 = 0, *b2 = 0, *Wfc = 0, *bfc = 0;
    int B = 0;
    for (int i = 0; i < n_in; i++) {
        int s = in_sizes[i];
        if      (s == 16384) W2  = (const float*)d_in[i];
        else if (s == 384)   W1  = (const float*)d_in[i];
        else if (s == 256)   Wfc = (const float*)d_in[i];
        else if (s == 2)     bfc = (const float*)d_in[i];
        else if (s == 128)   { if (!b1) b1 = (const float*)d_in[i];
                               else     b2 = (const float*)d_in[i]; }
        else if (s > 16384)  { x = (const float*)d_in[i]; B = s / (NN * 3); }
    }
    float* out = (float*)d_out;

    w2_split_kernel<<<32, 512>>>(W2);

    const int grid = (B + SPB - 1) / SPB;
    cudaFuncSetAttribute(gcn_hmma_kernel,
                         cudaFuncAttributeMaxDynamicSharedMemorySize, SMEM_BYTES);
    gcn_hmma_kernel<<<grid, THREADS, SMEM_BYTES>>>(x, W1, b1, b2, Wfc, bfc,
                                                   out, B);
}

// round 13
// speedup vs baseline: 1.5779x; 1.1154x over previous
#include <cuda_runtime.h>
#include <cuda_bf16.h>
#include <cstdint>

// ---------------------------------------------------------------------------
// Fused GCN (BODY_25, fixed topology), HMMA bf16 split GEMM, R13:
//   PERSISTENT blocks (grid = #SMs), each loops over tiles of SPB=5 samples.
//   Per tile, 2 barriers: R1 = GEMM + G-store + next-tile AGG1;
//   R2 = fused pool+FC (warps 0..ns-1)  ||  next-tile H1 build (warps 5..15).
//   A(hi/lo), B(hi/lo), G all have dedicated SMEM buffers (213 KB).
// ---------------------------------------------------------------------------

#define NN      25
#define HID     128
#define SPB     5
#define THREADS 512
#define LDA     272          // A/B tile row stride in BYTES (136 bf16)
#define LDGf    132          // G row stride in floats

typedef unsigned long long u64;

// ---- compile-time normalized CSR (rows = dst), verified R6-R12 ----
__device__ constexpr float RSQ[6] = {0.f, 1.f, 0.70710678118654752f,
                                     0.57735026918962576f, 0.5f,
                                     0.44721359549995794f};
__device__ constexpr int RP[26]  = {0,3,8,10,12,13,15,17,18,21,23,25,28,30,32,
                                    35,37,39,40,41,43,44,45,47,48,49};
__device__ constexpr int COL[49] = {0,15,16, 1,0,2,5,8, 2,3, 3,4, 4, 5,6, 6,7, 7,
                                    8,9,12, 9,10, 10,11, 11,22,24, 12,13, 13,14,
                                    14,19,21, 15,17, 16,18, 17, 18, 19,20, 20, 21,
                                    22,23, 23, 24};
__device__ constexpr int DEGI[25] = {3,5,2,2,1,2,2,1,3,2,2,3,2,2,3,2,2,1,1,2,1,1,2,1,1};
__device__ constexpr int DEGO[25] = {2,1,2,2,2,2,2,2,2,2,2,2,2,2,2,2,2,2,2,2,2,2,2,2,2};
__device__ constexpr float EW(int n, int e) {
    return RSQ[DEGI[n]] * RSQ[DEGO[COL[e]]];
}

// ---- W2 pre-split scratch: [k][n] bf16, padded rows; hi then lo ----
__device__ __align__(16) unsigned char g_w2[2 * 128 * LDA];   // 69632 B

__global__ void w2_split_kernel(const float* __restrict__ W2) {
    int i = blockIdx.x * blockDim.x + threadIdx.x;   // i = k*128 + n
    if (i < HID * HID) {
        int k = i >> 7, n = i & 127;
        float w = W2[i];
        __nv_bfloat16 hi = __float2bfloat16(w);
        __nv_bfloat16 lo = __float2bfloat16(w - __bfloat162float(hi));
        uint32_t off = (uint32_t)k * LDA + (uint32_t)n * 2;
        *(__nv_bfloat16*)(g_w2 + off)              = hi;
        *(__nv_bfloat16*)(g_w2 + 128 * LDA + off)  = lo;
    }
}

// ---- SMEM byte layout ----
// A_HI [0,34816) A_LO [34816,69632) B_HI [69632,104448) B_LO [104448,139264)
// G fp32 [139264, 206848)  (128 x LDGf)
// smalls (floats) at 206848: sA1[2][384], W1[384], b1[128], b2[128],
//                            Fc[256], Bf[4]
constexpr int A_HI = 0, A_LO = 34816, B_HI = 69632, B_LO = 104448,
              G_OFF = 139264, SMALLB = 206848;
constexpr int FA1 = 0, FW1 = 768, FB1 = 1152, FB2 = 1280,
              FFC = 1408, FBF = 1664, FEND = 1668;
constexpr int SMEM_BYTES = SMALLB + FEND * 4;       // 213520

__device__ __forceinline__ uint32_t smem_u32(const void* p) {
    uint32_t a;
    asm("{ .reg .u64 t; cvta.to.shared.u64 t, %1; cvt.u32.u64 %0, t; }"
        : "=r"(a) : "l"(p));
    return a;
}

#define LDSM_X4(r0, r1, r2, r3, addr)                                          \
    asm volatile("ldmatrix.sync.aligned.m8n8.x4.shared.b16 {%0,%1,%2,%3}, [%4];" \
        : "=r"(r0), "=r"(r1), "=r"(r2), "=r"(r3) : "r"(addr))
#define LDSM_X4T(r0, r1, r2, r3, addr)                                         \
    asm volatile("ldmatrix.sync.aligned.m8n8.x4.trans.shared.b16 {%0,%1,%2,%3}, [%4];" \
        : "=r"(r0), "=r"(r1), "=r"(r2), "=r"(r3) : "r"(addr))
#define MMA16816(acc, a0, a1, a2, a3, bb0, bb1)                                \
    asm volatile("mma.sync.aligned.m16n8k16.row.col.f32.bf16.bf16.f32 "        \
        "{%0,%1,%2,%3}, {%4,%5,%6,%7}, {%8,%9}, {%0,%1,%2,%3};"                \
        : "+f"((acc)[0]), "+f"((acc)[1]), "+f"((acc)[2]), "+f"((acc)[3])       \
        : "r"(a0), "r"(a1), "r"(a2), "r"(a3), "r"(bb0), "r"(bb1))

__device__ __forceinline__ uint32_t split_pack(float v0, float v1,
                                               uint32_t& lo_pack) {
    __nv_bfloat16 h0 = __float2bfloat16(v0);
    __nv_bfloat16 h1 = __float2bfloat16(v1);
    __nv_bfloat16 l0 = __float2bfloat16(v0 - __bfloat162float(h0));
    __nv_bfloat16 l1 = __float2bfloat16(v1 - __bfloat162float(h1));
    lo_pack = ((uint32_t)__bfloat16_as_ushort(l1) << 16)
            | __bfloat16_as_ushort(l0);
    return ((uint32_t)__bfloat16_as_ushort(h1) << 16)
         | __bfloat16_as_ushort(h0);
}

// AGG1 for one tile into sa1 (only threads tid < ns*3 do work)
__device__ __forceinline__ void agg1(const float* __restrict__ x, int tile,
                                     int B, float* sa1, int tid) {
    const int ns = min(SPB, B - tile * SPB);
    if (tid < ns * 3) {
        int s = tid / 3, f = tid - 3 * s;
        const float* xs = x + (long long)(tile * SPB + s) * (NN * 3) + f;
        float xv[NN];
        #pragma unroll
        for (int n = 0; n < NN; n++) xv[n] = __ldg(xs + n * 3);
        #pragma unroll
        for (int n = 0; n < NN; n++) {
            float t = 0.f;
            #pragma unroll
            for (int e = RP[n]; e < RP[n + 1]; e++)
                t = fmaf(EW(n, e), xv[COL[e]], t);
            sa1[(s * NN + n) * 3 + f] = t;
        }
    }
}

// H1 rows [r0, r0+nr) -> A_hi/A_lo, lane owns 4 columns (conflict-free)
__device__ __forceinline__ void phase1_rows(unsigned char* smb,
                                            const float* sW1, const float* sB1,
                                            const float* sa1, int r0, int nr,
                                            int nsn, int lane) {
    const float4 w0 = *(const float4*)(sW1 +       4 * lane);
    const float4 w1 = *(const float4*)(sW1 + 128 + 4 * lane);
    const float4 w2 = *(const float4*)(sW1 + 256 + 4 * lane);
    const float4 bb = *(const float4*)(sB1 +       4 * lane);
    unsigned char* baseH = smb + A_HI + 8 * lane;
    unsigned char* baseL = smb + A_LO + 8 * lane;
    for (int r = 0; r < nr; r++) {
        const int m  = r0 + r;
        const int mc = min(m, nsn - 1);
        const float a0 = sa1[mc * 3 + 0];
        const float a1 = sa1[mc * 3 + 1];
        const float a2 = sa1[mc * 3 + 2];
        float v0 = fmaxf(bb.x + a0 * w0.x + a1 * w1.x + a2 * w2.x, 0.f);
        float v1 = fmaxf(bb.y + a0 * w0.y + a1 * w1.y + a2 * w2.y, 0.f);
        float v2 = fmaxf(bb.z + a0 * w0.z + a1 * w1.z + a2 * w2.z, 0.f);
        float v3 = fmaxf(bb.w + a0 * w0.w + a1 * w1.w + a2 * w2.w, 0.f);
        uint32_t lp0, lp1;
        uint32_t hp0 = split_pack(v0, v1, lp0);
        uint32_t hp1 = split_pack(v2, v3, lp1);
        *(uint2*)(baseH + m * LDA) = make_uint2(hp0, hp1);
        *(uint2*)(baseL + m * LDA) = make_uint2(lp0, lp1);
    }
}

__global__ void __launch_bounds__(THREADS, 1)
gcn_hmma_persistent(const float* __restrict__ x,
                    const float* __restrict__ W1, const float* __restrict__ b1,
                    const float* __restrict__ b2,
                    const float* __restrict__ Wfc, const float* __restrict__ bfc,
                    float* __restrict__ out, int B)
{
    extern __shared__ __align__(16) unsigned char smb[];
    float* sG  = (float*)(smb + G_OFF);
    float* sSm = (float*)(smb + SMALLB);
    float* sA1 = sSm + FA1;          // 2 x 384
    float* sW1 = sSm + FW1;
    float* sB1 = sSm + FB1;
    float* sB2 = sSm + FB2;
    float* sFc = sSm + FFC;
    float* sBf = sSm + FBF;

    const uint32_t sb = smem_u32(smb);
    const int tid = threadIdx.x;
    const int wid = tid >> 5, lane = tid & 31;
    const int ntiles = (B + SPB - 1) / SPB;

    // ---- one-time staging ---------------------------------------------------
    if (tid < 384) sW1[tid] = W1[tid];
    if (tid < 128) { sB1[tid] = b1[tid]; sB2[tid] = b2[tid]; }
    if (tid < 256) sFc[tid] = Wfc[tid];
    if (tid < 2)   sBf[tid] = bfc[tid];
    {   // B hi/lo tiles: 69632 B = 4352 uint4
        const uint4* src = (const uint4*)g_w2;
        uint4* dst = (uint4*)(smb + B_HI);
        #pragma unroll
        for (int i = tid; i < 4352; i += THREADS) dst[i] = src[i];
    }

    int t = blockIdx.x;
    if (t >= ntiles) return;

    // prologue: AGG1(t) -> buf 0, then H1(t) by all 16 warps (8 rows each)
    agg1(x, t, B, sA1, tid);
    __syncthreads();
    {
        const int nsn = min(SPB, B - t * SPB) * NN;
        phase1_rows(smb, sW1, sB1, sA1, wid * 8, 8, nsn, lane);
    }

    const int mt = wid & 7, nh = wid >> 3;
    const int m0 = mt << 4;
    int buf = 0;

    for (; t < ntiles; t += gridDim.x) {
        const int ns = min(SPB, B - t * SPB);
        const int tn = t + gridDim.x;
        __syncthreads();               // A(t) ready; G free

        // ---- R1: AGG1(t+1) [few threads], GEMM(t), G store -----------------
        if (tn < ntiles) agg1(x, tn, B, sA1 + 384 * (buf ^ 1), tid);

        float acc[8][4];
        #pragma unroll
        for (int j = 0; j < 8; j++)
            #pragma unroll
            for (int q = 0; q < 4; q++) acc[j][q] = 0.f;

        {
            const uint32_t aOff = (uint32_t)(m0 + (lane & 15)) * LDA
                                + ((lane >> 4) << 4);
            const uint32_t bOff = (uint32_t)(lane & 15) * LDA
                                + ((lane >> 4) << 4) + (nh << 7);
            const uint32_t aH = sb + A_HI + aOff;
            const uint32_t aL = sb + A_LO + aOff;
            const uint32_t bH = sb + B_HI + bOff;
            const uint32_t bL = sb + B_LO + bOff;

            #pragma unroll 1
            for (int kk = 0; kk < 8; kk++) {
                const uint32_t ka = kk * 32;
                const uint32_t kb = kk * (16 * LDA);
                uint32_t ah[4], al[4];
                LDSM_X4(ah[0], ah[1], ah[2], ah[3], aH + ka);
                LDSM_X4(al[0], al[1], al[2], al[3], aL + ka);
                #pragma unroll
                for (int nb = 0; nb < 4; nb++) {
                    uint32_t bh[4], bl[4];
                    LDSM_X4T(bh[0], bh[1], bh[2], bh[3], bH + kb + nb * 32);
                    LDSM_X4T(bl[0], bl[1], bl[2], bl[3], bL + kb + nb * 32);
                    MMA16816(acc[2*nb  ], ah[0], ah[1], ah[2], ah[3], bh[0], bh[1]);
                    MMA16816(acc[2*nb+1], ah[0], ah[1], ah[2], ah[3], bh[2], bh[3]);
                    MMA16816(acc[2*nb  ], al[0], al[1], al[2], al[3], bh[0], bh[1]);
                    MMA16816(acc[2*nb+1], al[0], al[1], al[2], al[3], bh[2], bh[3]);
                    MMA16816(acc[2*nb  ], ah[0], ah[1], ah[2], ah[3], bl[0], bl[1]);
                    MMA16816(acc[2*nb+1], ah[0], ah[1], ah[2], ah[3], bl[2], bl[3]);
                }
            }
        }

        {   // G store (own buffer -> no barrier needed before it)
            const int g  = lane >> 2;
            const int t2 = (lane & 3) << 1;
            const int c0 = (nh << 6) + t2;
            #pragma unroll
            for (int na = 0; na < 8; na++) {
                const int col = c0 + (na << 3);
                *(float2*)(sG + (m0 + g)     * LDGf + col) =
                    make_float2(acc[na][0], acc[na][1]);
                *(float2*)(sG + (m0 + 8 + g) * LDGf + col) =
                    make_float2(acc[na][2], acc[na][3]);
            }
        }
        __syncthreads();

        // ---- R2: fused pool+FC (warps 0..ns-1) || H1(t+1) (warps 5..15) ----
        if (wid < ns) {
            const float4* G4 = (const float4*)sG;
            const int base = wid * NN;
            const float4 bb = ((const float4*)sB2)[lane];
            float4 pooled = make_float4(0.f, 0.f, 0.f, 0.f);
            #pragma unroll
            for (int n = 0; n < NN; n++) {
                float4 tt = make_float4(0.f, 0.f, 0.f, 0.f);
                #pragma unroll
                for (int e = RP[n]; e < RP[n + 1]; e++) {
                    const float w = EW(n, e);
                    float4 g = G4[(base + COL[e]) * (LDGf / 4) + lane];
                    tt.x = fmaf(w, g.x, tt.x);
                    tt.y = fmaf(w, g.y, tt.y);
                    tt.z = fmaf(w, g.z, tt.z);
                    tt.w = fmaf(w, g.w, tt.w);
                }
                pooled.x += fmaxf(tt.x + bb.x, 0.f);
                pooled.y += fmaxf(tt.y + bb.y, 0.f);
                pooled.z += fmaxf(tt.z + bb.z, 0.f);
                pooled.w += fmaxf(tt.w + bb.w, 0.f);
            }
            const float4 f01 = ((const float4*)sFc)[2 * lane];
            const float4 f23 = ((const float4*)sFc)[2 * lane + 1];
            float p0 = 0.04f * (pooled.x * f01.x + pooled.y * f01.z
                              + pooled.z * f23.x + pooled.w * f23.z);
            float p1 = 0.04f * (pooled.x * f01.y + pooled.y * f01.w
                              + pooled.z * f23.y + pooled.w * f23.w);
            #pragma unroll
            for (int o = 16; o; o >>= 1) {
                p0 += __shfl_xor_sync(0xffffffff, p0, o);
                p1 += __shfl_xor_sync(0xffffffff, p1, o);
            }
            if (lane == 0) {
                int b = t * SPB + wid;
                out[b * 2 + 0] = p0 + sBf[0];
                out[b * 2 + 1] = p1 + sBf[1];
            }
        } else if (wid >= 5 && tn < ntiles) {
            const int nsn2 = min(SPB, B - tn * SPB) * NN;
            const int p  = wid - 5;        // 0..10
            const int r0 = p * 12;
            const int nr = min(12, 128 - r0);
            phase1_rows(smb, sW1, sB1, sA1 + 384 * (buf ^ 1), r0, nr, nsn2, lane);
        }
        buf ^= 1;
    }
}

extern "C" void kernel_launch(void* const* d_in, const int* in_sizes, int n_in,
                              void* d_out, int out_size)
{
    const float *x = 0, *W1 = 0, *b1 = 0, *W2 = 0, *b2 = 0, *Wfc = 0, *bfc = 0;
    int B = 0;
    for (int i = 0; i < n_in; i++) {
        int s = in_sizes[i];
        if      (s == 16384) W2  = (const float*)d_in[i];
        else if (s == 384)   W1  = (const float*)d_in[i];
        else if (s == 256)   Wfc = (const float*)d_in[i];
        else if (s == 2)     bfc = (const float*)d_in[i];
        else if (s == 128)   { if (!b1) b1 = (const float*)d_in[i];
                               else     b2 = (const float*)d_in[i]; }
        else if (s > 16384)  { x = (const float*)d_in[i]; B = s / (NN * 3); }
    }
    float* out = (float*)d_out;

    w2_split_kernel<<<32, 512>>>(W2);

    int sms = 148;
    cudaDeviceGetAttribute(&sms, cudaDevAttrMultiProcessorCount, 0);
    const int ntiles = (B + SPB - 1) / SPB;
    const int grid = (ntiles < sms) ? ntiles : sms;

    cudaFuncSetAttribute(gcn_hmma_persistent,
                         cudaFuncAttributeMaxDynamicSharedMemorySize, SMEM_BYTES);
    gcn_hmma_persistent<<<grid, THREADS, SMEM_BYTES>>>(x, W1, b1, b2, Wfc, bfc,
                                                       out, B);
}